// round 10
// baseline (speedup 1.0000x reference)
#include <cuda_runtime.h>
#include <cuda_bf16.h>

// out[i] = 0.1 * x[i] * sum_j A[i][j] * (1 - x[j])
// A: 16384^2 fp32 = 1.074 GB streamed once -> HBM-bound; CTA-per-row version
// measured 152.9 us / 6.92 TB/s (87.3% DRAM). This version: persistent
// warp-per-row, shuffle-only reduction, zero barriers, one residency wave.
//  - grid = 152 SMs (GB300) x 8 CTAs = 1216, 256 thr -> 9728 warps
//  - each warp streams whole rows (row += 9728); per-instruction access =
//    32 lanes x float4 = 512 B contiguous, identical coalescing to before
//  - 4 front-batched A LDG.128 per iter (DRAM MLP); x loads are L1-hits,
//    interleaved with FMAs to keep live regs <= 32 (occ-8 cap)

__global__ __launch_bounds__(256, 8)
void matvec_warp_kernel(const float* __restrict__ A,
                        const float* __restrict__ x,
                        float* __restrict__ out,
                        int n) {
    const int lane = threadIdx.x & 31;
    const int warp_global = (blockIdx.x * (blockDim.x >> 5)) + (threadIdx.x >> 5);
    const int warp_count  = gridDim.x * (blockDim.x >> 5);
    const int nv = n >> 2;  // float4 per row
    const float4* __restrict__ x4 = reinterpret_cast<const float4*>(x);

    #pragma unroll 1
    for (int row = warp_global; row < n; row += warp_count) {
        const float4* __restrict__ Arow =
            reinterpret_cast<const float4*>(A + (size_t)row * (size_t)n);

        float s0 = 0.f, s1 = 0.f, s2 = 0.f, s3 = 0.f;
        int j = lane;
        #pragma unroll 1
        for (; j + 96 < nv; j += 128) {
            // front-batch the DRAM stream (MLP_p1 = 4 per warp)
            float4 a0 = __ldg(Arow + j);
            float4 a1 = __ldg(Arow + j + 32);
            float4 a2 = __ldg(Arow + j + 64);
            float4 a3 = __ldg(Arow + j + 96);
            // x is L1-resident (64 KB); interleave to cap live registers
            float4 b = __ldg(x4 + j);
            s0 = fmaf(a0.x, 1.f - b.x, fmaf(a0.y, 1.f - b.y,
                 fmaf(a0.z, 1.f - b.z, fmaf(a0.w, 1.f - b.w, s0))));
            b = __ldg(x4 + j + 32);
            s1 = fmaf(a1.x, 1.f - b.x, fmaf(a1.y, 1.f - b.y,
                 fmaf(a1.z, 1.f - b.z, fmaf(a1.w, 1.f - b.w, s1))));
            b = __ldg(x4 + j + 64);
            s2 = fmaf(a2.x, 1.f - b.x, fmaf(a2.y, 1.f - b.y,
                 fmaf(a2.z, 1.f - b.z, fmaf(a2.w, 1.f - b.w, s2))));
            b = __ldg(x4 + j + 96);
            s3 = fmaf(a3.x, 1.f - b.x, fmaf(a3.y, 1.f - b.y,
                 fmaf(a3.z, 1.f - b.z, fmaf(a3.w, 1.f - b.w, s3))));
        }
        #pragma unroll 1
        for (; j < nv; j += 32) {
            float4 a = __ldg(Arow + j);
            float4 b = __ldg(x4 + j);
            s0 = fmaf(a.x, 1.f - b.x, fmaf(a.y, 1.f - b.y,
                 fmaf(a.z, 1.f - b.z, fmaf(a.w, 1.f - b.w, s0))));
        }
        float s = (s0 + s1) + (s2 + s3);

        // shuffle-only reduction: no smem, no barriers
        #pragma unroll
        for (int off = 16; off > 0; off >>= 1)
            s += __shfl_down_sync(0xFFFFFFFFu, s, off);

        if (lane == 0)
            out[row] = 0.1f * x[row] * s;
    }
}

extern "C" void kernel_launch(void* const* d_in, const int* in_sizes, int n_in,
                              void* d_out, int out_size) {
    // metadata order: t, x, A
    const float* x = (const float*)d_in[1];
    const float* A = (const float*)d_in[2];
    float* out = (float*)d_out;
    const int n = in_sizes[1];  // 16384

    // one full residency wave: 152 SMs (GB300) x 8 CTAs
    matvec_warp_kernel<<<1216, 256>>>(A, x, out, n);
}

// round 13
// speedup vs baseline: 1.0859x; 1.0859x over previous
#include <cuda_runtime.h>
#include <cuda_bf16.h>

// out[i] = 0.1 * x[i] * sum_j A[i][j] * (1 - x[j])
// HBM-bound: A = 1.074 GB streamed once. Measured so far:
//   CTA-per-row, 16384 blocks:  152.9 us, DRAM 87.3%, occ 99.6%   <- best
//   warp-per-row, 1216 blocks:  180.7 us, DRAM 77.1%  <- FAILED: 608 MB
//     concurrent footprint blew the 256 MB TLB reach (304 live 2MB pages
//     vs 128 entries) + 68%-populated second round.
// This version: PERSISTENT CTA-per-row. Same block-cooperative inner loop
// as the 152.9 us kernel, but grid = one residency wave (152 SM x 8) and
// each CTA strides rows by 1216. Active footprint = 1216 rows = 76 MB
// (TLB-resident sliding window, same as the good version) while removing
// 14 wave transitions + 16384 CLC schedulings.
//  - 4 front-batched A LDG.128 (DRAM MLP); x loads L1-hit, interleaved to
//    keep regs <= 32 (occ-8 cap)
//  - parity-indexed smem buffer -> one __syncthreads per row, no trailing bar
//    (audited: warps can lead warp 0 by at most one row; same-parity rewrite
//     happens two rows later, strictly after the intervening barrier)

__global__ __launch_bounds__(256, 8)
void matvec_persist_kernel(const float* __restrict__ A,
                           const float* __restrict__ x,
                           float* __restrict__ out,
                           int n) {
    const int nv = n >> 2;  // float4 per row
    const float4* __restrict__ x4 = reinterpret_cast<const float4*>(x);
    const int lane = threadIdx.x & 31;
    const int wid  = threadIdx.x >> 5;

    __shared__ float warp_sums[2][8];

    int parity = 0;
    #pragma unroll 1
    for (int row = blockIdx.x; row < n; row += gridDim.x, parity ^= 1) {
        const float4* __restrict__ Arow =
            reinterpret_cast<const float4*>(A + (size_t)row * (size_t)n);

        float s0 = 0.f, s1 = 0.f, s2 = 0.f, s3 = 0.f;
        int j = threadIdx.x;
        #pragma unroll 1
        for (; j + 768 < nv; j += 1024) {
            // front-batch the DRAM stream (4 x LDG.128 per thread)
            float4 a0 = __ldg(Arow + j);
            float4 a1 = __ldg(Arow + j + 256);
            float4 a2 = __ldg(Arow + j + 512);
            float4 a3 = __ldg(Arow + j + 768);
            // x is L1-resident; interleave to cap live registers at ~32
            float4 b = __ldg(x4 + j);
            s0 = fmaf(a0.x, 1.f - b.x, fmaf(a0.y, 1.f - b.y,
                 fmaf(a0.z, 1.f - b.z, fmaf(a0.w, 1.f - b.w, s0))));
            b = __ldg(x4 + j + 256);
            s1 = fmaf(a1.x, 1.f - b.x, fmaf(a1.y, 1.f - b.y,
                 fmaf(a1.z, 1.f - b.z, fmaf(a1.w, 1.f - b.w, s1))));
            b = __ldg(x4 + j + 512);
            s2 = fmaf(a2.x, 1.f - b.x, fmaf(a2.y, 1.f - b.y,
                 fmaf(a2.z, 1.f - b.z, fmaf(a2.w, 1.f - b.w, s2))));
            b = __ldg(x4 + j + 768);
            s3 = fmaf(a3.x, 1.f - b.x, fmaf(a3.y, 1.f - b.y,
                 fmaf(a3.z, 1.f - b.z, fmaf(a3.w, 1.f - b.w, s3))));
        }
        #pragma unroll 1
        for (; j < nv; j += 256) {
            float4 a = __ldg(Arow + j);
            float4 b = __ldg(x4 + j);
            s0 = fmaf(a.x, 1.f - b.x, fmaf(a.y, 1.f - b.y,
                 fmaf(a.z, 1.f - b.z, fmaf(a.w, 1.f - b.w, s0))));
        }
        float s = (s0 + s1) + (s2 + s3);

        #pragma unroll
        for (int off = 16; off > 0; off >>= 1)
            s += __shfl_down_sync(0xFFFFFFFFu, s, off);

        if (lane == 0) warp_sums[parity][wid] = s;
        __syncthreads();

        if (wid == 0) {
            s = (lane < 8) ? warp_sums[parity][lane] : 0.f;
            #pragma unroll
            for (int off = 4; off > 0; off >>= 1)
                s += __shfl_down_sync(0xFFFFFFFFu, s, off);
            if (lane == 0)
                out[row] = 0.1f * x[row] * s;
        }
        // no trailing barrier: next row writes warp_sums[parity^1]
    }
}

extern "C" void kernel_launch(void* const* d_in, const int* in_sizes, int n_in,
                              void* d_out, int out_size) {
    // metadata order: t, x, A
    const float* x = (const float*)d_in[1];
    const float* A = (const float*)d_in[2];
    float* out = (float*)d_out;
    const int n = in_sizes[1];  // 16384

    // one full residency wave: 152 SMs (GB300) x 8 CTAs
    matvec_persist_kernel<<<1216, 256>>>(A, x, out, n);
}